// round 1
// baseline (speedup 1.0000x reference)
#include <cuda_runtime.h>
#include <math.h>

#define NN   8192
#define DIN  512
#define DHID 256
#define DOUT 128
#define CAP  256        // max edges per row (Poisson mean 32.8; P(>256) ~ 0)
#define NEG  0.25f

// ---------------- scratch (device globals; no allocs allowed) ----------------
__device__ float g_y1[NN * DHID];
__device__ float g_x1[NN * DHID];
__device__ float g_y2[NN * DHID];
__device__ float g_x2[NN * DHID];
__device__ float g_h [NN * DOUT];
__device__ float g_f1[NN];
__device__ float g_f2[NN];
__device__ int   g_cnt [NN];
__device__ int   g_ecol[NN * CAP];
__device__ float g_eval[NN * CAP];
__device__ float g_part[64 * DOUT];
__device__ float g_hmean[DOUT];

__device__ __forceinline__ float leaky(float x) { return x >= 0.f ? x : NEG * x; }

// ---------------- 1) edge extraction: one dense pass over adj ----------------
// One block per row. Row (32KB) staged in smem; each thread owns the strided
// column set {t, t+256, ...} (deterministic ordering), block-scan for offsets.
__global__ void k_extract(const float* __restrict__ adj) {
    __shared__ float srow[NN];
    __shared__ int   scnt[256];
    const int row = blockIdx.x, tid = threadIdx.x;
    const float* arow = adj + (size_t)row * NN;
    for (int j = tid; j < NN; j += 256) srow[j] = arow[j];
    __syncthreads();

    int c = 0;
#pragma unroll
    for (int i = 0; i < 32; i++) if (srow[i * 256 + tid] > 0.f) c++;
    scnt[tid] = c;
    __syncthreads();
    // Hillis-Steele inclusive scan over 256 counts
    for (int off = 1; off < 256; off <<= 1) {
        int v = scnt[tid];
        if (tid >= off) v += scnt[tid - off];
        __syncthreads();
        scnt[tid] = v;
        __syncthreads();
    }
    const int my_off = scnt[tid] - c;
    if (tid == 0) {
        int total = scnt[255];
        g_cnt[row] = total < CAP ? total : CAP;
    }
    const int base = row * CAP;
    int k = 0;
#pragma unroll
    for (int i = 0; i < 32; i++) {
        float v = srow[i * 256 + tid];
        if (v > 0.f) {
            int p = my_off + k;
            if (p < CAP) { g_ecol[base + p] = i * 256 + tid; g_eval[base + p] = v; }
            k++;
        }
    }
}

// ---------------- 2) fp32 SGEMM: C[M,Nn] = A[M,K] @ B[K,Nn] ----------------
// BM=128, BN=64, BK=16, 128 threads, 8x8 per-thread microtile.
#define BM 128
#define BN 64
#define BK 16
__global__ void k_sgemm(const float* __restrict__ A, const float* __restrict__ B,
                        float* __restrict__ C, int M, int Nn, int K) {
    __shared__ float As[BK][BM];
    __shared__ float Bs[BK][BN];
    const int tid = threadIdx.x;
    const int m0 = blockIdx.x * BM;
    const int n0 = blockIdx.y * BN;
    const int tm = (tid >> 3) * 8;   // 0..120
    const int tn = (tid & 7) * 8;    // 0..56

    float acc[8][8];
#pragma unroll
    for (int i = 0; i < 8; i++)
#pragma unroll
        for (int j = 0; j < 8; j++) acc[i][j] = 0.f;

    for (int kt = 0; kt < K; kt += BK) {
        // stage A: thread loads row (m0+tid), 16 k-values
        const float* ap = A + (size_t)(m0 + tid) * K + kt;
        float4 av0 = *(const float4*)(ap);
        float4 av1 = *(const float4*)(ap + 4);
        float4 av2 = *(const float4*)(ap + 8);
        float4 av3 = *(const float4*)(ap + 12);
        // stage B: two float4 per thread (rows tid>>4 and tid>>4 + 8)
        const float* bp = B + (size_t)(kt + (tid >> 4)) * Nn + n0 + (tid & 15) * 4;
        float4 bv0 = *(const float4*)(bp);
        float4 bv1 = *(const float4*)(bp + (size_t)8 * Nn);

        __syncthreads();   // previous tile's compute finished
        As[0][tid] = av0.x;  As[1][tid] = av0.y;  As[2][tid] = av0.z;  As[3][tid] = av0.w;
        As[4][tid] = av1.x;  As[5][tid] = av1.y;  As[6][tid] = av1.z;  As[7][tid] = av1.w;
        As[8][tid] = av2.x;  As[9][tid] = av2.y;  As[10][tid] = av2.z; As[11][tid] = av2.w;
        As[12][tid] = av3.x; As[13][tid] = av3.y; As[14][tid] = av3.z; As[15][tid] = av3.w;
        *(float4*)&Bs[(tid >> 4)][(tid & 15) * 4]     = bv0;
        *(float4*)&Bs[(tid >> 4) + 8][(tid & 15) * 4] = bv1;
        __syncthreads();

#pragma unroll
        for (int k = 0; k < BK; k++) {
            float a[8], b[8];
            *(float4*)(a)     = *(const float4*)&As[k][tm];
            *(float4*)(a + 4) = *(const float4*)&As[k][tm + 4];
            *(float4*)(b)     = *(const float4*)&Bs[k][tn];
            *(float4*)(b + 4) = *(const float4*)&Bs[k][tn + 4];
#pragma unroll
            for (int i = 0; i < 8; i++)
#pragma unroll
                for (int j = 0; j < 8; j++) acc[i][j] = fmaf(a[i], b[j], acc[i][j]);
        }
    }
    // epilogue
#pragma unroll
    for (int i = 0; i < 8; i++) {
        float* cp = C + (size_t)(m0 + tm + i) * Nn + n0 + tn;
        *(float4*)(cp)     = make_float4(acc[i][0], acc[i][1], acc[i][2], acc[i][3]);
        *(float4*)(cp + 4) = make_float4(acc[i][4], acc[i][5], acc[i][6], acc[i][7]);
    }
}

// ---------------- 3) sparse SpMM + bias + leaky: out = leaky(adj@y + b) -----
__global__ void k_spmm(const float* __restrict__ y, const float* __restrict__ bias,
                       float* __restrict__ out) {
    __shared__ int   scol[CAP];
    __shared__ float sval[CAP];
    const int row = blockIdx.x, tid = threadIdx.x;   // 256 threads
    const int cnt = g_cnt[row];
    for (int t = tid; t < cnt; t += 256) {
        scol[t] = g_ecol[row * CAP + t];
        sval[t] = g_eval[row * CAP + t];
    }
    __syncthreads();
    float acc = 0.f;
    for (int t = 0; t < cnt; t++)
        acc = fmaf(sval[t], y[(size_t)scol[t] * DHID + tid], acc);
    out[(size_t)row * DHID + tid] = leaky(acc + bias[tid]);
}

// ---------------- 4) f1 = h@a1, f2 = h@a2 (warp per row) --------------------
__global__ void k_f12(const float* __restrict__ h, const float* __restrict__ a) {
    const int warp = (blockIdx.x * blockDim.x + threadIdx.x) >> 5;
    const int lane = threadIdx.x & 31;
    if (warp >= NN) return;
    const float* hr = h + (size_t)warp * DOUT;
    float s1 = 0.f, s2 = 0.f;
#pragma unroll
    for (int q = 0; q < 4; q++) {
        int c = lane + q * 32;
        float hv = hr[c];
        s1 = fmaf(hv, a[c], s1);
        s2 = fmaf(hv, a[DOUT + c], s2);
    }
#pragma unroll
    for (int o = 16; o; o >>= 1) {
        s1 += __shfl_down_sync(0xffffffffu, s1, o);
        s2 += __shfl_down_sync(0xffffffffu, s2, o);
    }
    if (lane == 0) { g_f1[warp] = s1; g_f2[warp] = s2; }
}

// ---------------- 5) column mean of h (for zero-edge rows) ------------------
__global__ void k_part(const float* __restrict__ h) {
    const int b = blockIdx.x, c = threadIdx.x;   // 64 blocks x 128 threads
    float s = 0.f;
    for (int r = 0; r < 128; r++) s += h[(size_t)(b * 128 + r) * DOUT + c];
    g_part[b * DOUT + c] = s;
}
__global__ void k_mean() {
    const int c = threadIdx.x;
    float s = 0.f;
    for (int b = 0; b < 64; b++) s += g_part[b * DOUT + c];
    g_hmean[c] = s * (1.f / NN);
}

// ---------------- 6) sparse masked softmax + h_prime + leaky + split --------
__global__ void k_attn(const float* __restrict__ h, float* __restrict__ out) {
    __shared__ float se[CAP];
    __shared__ int   scol[CAP];
    __shared__ float sred[128];
    const int row = blockIdx.x, tid = threadIdx.x;   // 128 threads
    const int cnt = g_cnt[row];

    if (cnt == 0) {
        // softmax over all-equal MASK_VAL -> uniform -> mean of h
        float v = leaky(g_hmean[tid]);
        if (tid < 64) out[(size_t)row * 64 + tid] = v;
        else          out[(size_t)NN * 64 + (size_t)row * 64 + (tid - 64)] = v;
        return;
    }

    const float f1i = g_f1[row];
    float lmax = -INFINITY;
    for (int t = tid; t < cnt; t += 128) {
        int j = g_ecol[row * CAP + t];
        float e = leaky(f1i + g_f2[j]);
        scol[t] = j;
        se[t] = e;
        lmax = fmaxf(lmax, e);
    }
    sred[tid] = lmax;
    __syncthreads();
    for (int s = 64; s; s >>= 1) {
        if (tid < s) sred[tid] = fmaxf(sred[tid], sred[tid + s]);
        __syncthreads();
    }
    const float m = sred[0];
    __syncthreads();   // all threads have read m before sred is reused

    float lsum = 0.f;
    for (int t = tid; t < cnt; t += 128) {
        float w = __expf(se[t] - m);
        se[t] = w;
        lsum += w;
    }
    sred[tid] = lsum;
    __syncthreads();
    for (int s = 64; s; s >>= 1) {
        if (tid < s) sred[tid] += sred[tid + s];
        __syncthreads();
    }
    const float invZ = 1.f / sred[0];

    float acc = 0.f;
    for (int t = 0; t < cnt; t++)
        acc = fmaf(se[t], h[(size_t)scol[t] * DOUT + tid], acc);
    float v = leaky(acc * invZ);
    if (tid < 64) out[(size_t)row * 64 + tid] = v;
    else          out[(size_t)NN * 64 + (size_t)row * 64 + (tid - 64)] = v;
}

// ---------------- launch ----------------------------------------------------
extern "C" void kernel_launch(void* const* d_in, const int* in_sizes, int n_in,
                              void* d_out, int out_size) {
    (void)in_sizes; (void)n_in; (void)out_size;
    const float* x   = (const float*)d_in[0];
    const float* adj = (const float*)d_in[1];
    const float* W1  = (const float*)d_in[2];
    const float* b1  = (const float*)d_in[3];
    const float* W2  = (const float*)d_in[4];
    const float* b2  = (const float*)d_in[5];
    const float* Wg  = (const float*)d_in[6];
    const float* a   = (const float*)d_in[7];
    float* out = (float*)d_out;

    void *p;
    cudaGetSymbolAddress(&p, g_y1); float* y1 = (float*)p;
    cudaGetSymbolAddress(&p, g_x1); float* x1 = (float*)p;
    cudaGetSymbolAddress(&p, g_y2); float* y2 = (float*)p;
    cudaGetSymbolAddress(&p, g_x2); float* x2 = (float*)p;
    cudaGetSymbolAddress(&p, g_h);  float* h  = (float*)p;

    k_extract<<<NN, 256>>>(adj);

    dim3 gh(NN / BM, DHID / BN);   // 64 x 4
    dim3 go(NN / BM, DOUT / BN);   // 64 x 2
    k_sgemm<<<gh, 128>>>(x,  W1, y1, NN, DHID, DIN);
    k_spmm<<<NN, 256>>>(y1, b1, x1);
    k_sgemm<<<gh, 128>>>(x1, W2, y2, NN, DHID, DHID);
    k_spmm<<<NN, 256>>>(y2, b2, x2);
    k_sgemm<<<go, 128>>>(x2, Wg, h,  NN, DOUT, DHID);

    k_f12 <<<NN / 8, 256>>>(h, a);
    k_part<<<64, 128>>>(h);
    k_mean<<<1, 128>>>();
    k_attn<<<NN, 128>>>(h, out);
}